// round 1
// baseline (speedup 1.0000x reference)
#include <cuda_runtime.h>

#define BS     4096
#define SEGLEN 8192
#define LAM1   8e-05f
#define LAM2   8e-05f

// Scratch (allocation-free rule: __device__ globals)
__device__ float g_smooth[BS];
__device__ float g_spars[BS];
__device__ int   g_ms[BS];

// ---------------------------------------------------------------------------
// Kernel 1: per-row sum, sum of squared adjacent diffs, first-occurrence argmax
// One block per row. 256 threads x 8 float4 = 8192 floats.
// ---------------------------------------------------------------------------
__global__ __launch_bounds__(256) void row_stats(const float* __restrict__ scores) {
    const int row = blockIdx.x;
    const float*  rf = scores + (size_t)row * SEGLEN;
    const float4* rp = (const float4*)rf;
    const int t = threadIdx.x;

    float sum = 0.f, sq = 0.f;
    float maxv = -1.f;
    int   maxi = 0;

#pragma unroll
    for (int k = 0; k < 8; k++) {
        const int v4 = k * 256 + t;   // float4 index; element index e = 4*v4
        const int e  = v4 * 4;
        float4 x = rp[v4];
        // neighbor for the boundary diff; last element of row has no diff term
        float nxt = (e + 4 < SEGLEN) ? __ldg(rf + e + 4) : x.w;

        sum += (x.x + x.y) + (x.z + x.w);
        float d0 = x.y - x.x, d1 = x.z - x.y, d2 = x.w - x.z, d3 = nxt - x.w;
        sq += d0 * d0 + d1 * d1 + d2 * d2 + d3 * d3;

        // strict > preserves first occurrence (per-thread indices increase with k)
        if (x.x > maxv) { maxv = x.x; maxi = e;     }
        if (x.y > maxv) { maxv = x.y; maxi = e + 1; }
        if (x.z > maxv) { maxv = x.z; maxi = e + 2; }
        if (x.w > maxv) { maxv = x.w; maxi = e + 3; }
    }

    // warp reduce (fixed order -> deterministic)
#pragma unroll
    for (int off = 16; off > 0; off >>= 1) {
        sum += __shfl_down_sync(0xFFFFFFFFu, sum, off);
        sq  += __shfl_down_sync(0xFFFFFFFFu, sq,  off);
        float ov = __shfl_down_sync(0xFFFFFFFFu, maxv, off);
        int   oi = __shfl_down_sync(0xFFFFFFFFu, maxi, off);
        if (ov > maxv || (ov == maxv && oi < maxi)) { maxv = ov; maxi = oi; }
    }

    __shared__ float ssum[8], ssq[8], smax[8];
    __shared__ int   sidx[8];
    const int w = t >> 5, l = t & 31;
    if (l == 0) { ssum[w] = sum; ssq[w] = sq; smax[w] = maxv; sidx[w] = maxi; }
    __syncthreads();

    if (t == 0) {
        float S = 0.f, Q = 0.f, M = -1.f;
        int I = 0;
#pragma unroll
        for (int i = 0; i < 8; i++) {
            S += ssum[i];
            Q += ssq[i];
            if (smax[i] > M || (smax[i] == M && sidx[i] < I)) { M = smax[i]; I = sidx[i]; }
        }
        g_spars[row]  = S;
        g_smooth[row] = Q;
        g_ms[row]     = I;
    }
}

// ---------------------------------------------------------------------------
// Kernel 2 (single block, 1024 threads):
//   margin[i] = sum_{j: label[j]==0} max(0, 1 - ms[i] + ms[j]) = T[ms[i]]
//   where T = suffix-sum applied twice to histogram of ms over negatives.
//   Then deterministic reduction of per-row losses over positive rows.
// ---------------------------------------------------------------------------
__global__ __launch_bounds__(1024) void finalize(const int* __restrict__ labels,
                                                 float* __restrict__ out) {
    __shared__ int   cnt[SEGLEN];   // histogram -> S1 -> T (in place)
    __shared__ int   ts[1024];      // cross-chunk scan temp
    __shared__ float red[1024];     // final float reduction

    const int t = threadIdx.x;
    const int base = t * 8;         // each thread owns bins [8t, 8t+8)

#pragma unroll
    for (int k = 0; k < 8; k++) cnt[base + k] = 0;
    __syncthreads();

    // histogram of argmax indices over negative rows
    for (int i = t; i < BS; i += 1024)
        if (labels[i] == 0) atomicAdd(&cnt[g_ms[i]], 1);
    __syncthreads();

    // two rounds of suffix-sum over 8192 bins
    for (int round = 0; round < 2; round++) {
        int c = 0;
#pragma unroll
        for (int k = 0; k < 8; k++) c += cnt[base + k];
        ts[t] = c;
        __syncthreads();

        // Hillis-Steele inclusive suffix scan over 1024 chunk totals
        for (int d = 1; d < 1024; d <<= 1) {
            int a = (t + d < 1024) ? ts[t + d] : 0;
            __syncthreads();
            ts[t] += a;
            __syncthreads();
        }

        int r = ts[t] - c;  // exclusive suffix: sum of chunks > t
#pragma unroll
        for (int k = 7; k >= 0; k--) {
            r += cnt[base + k];
            cnt[base + k] = r;
        }
        __syncthreads();
    }

    // per-positive-row loss, accumulated in fixed order
    float acc = 0.f;
    for (int i = t; i < BS; i += 1024) {
        if (labels[i] == 1) {
            int m      = g_ms[i];
            int margin = cnt[m];  // == T[m]
            acc += LAM1 * g_smooth[i] + LAM2 * g_spars[i] + (float)margin;
        }
    }

    red[t] = acc;
    __syncthreads();
#pragma unroll
    for (int s = 512; s > 0; s >>= 1) {
        if (t < s) red[t] += red[t + s];
        __syncthreads();
    }
    if (t == 0) out[0] = red[0] / (float)BS;
}

extern "C" void kernel_launch(void* const* d_in, const int* in_sizes, int n_in,
                              void* d_out, int out_size) {
    const float* scores = (const float*)d_in[0];
    const int*   labels = (const int*)d_in[1];
    float*       out    = (float*)d_out;

    row_stats<<<BS, 256>>>(scores);
    finalize<<<1, 1024>>>(labels, out);
}

// round 2
// speedup vs baseline: 1.1159x; 1.1159x over previous
#include <cuda_runtime.h>

#define BS     4096
#define SEGLEN 8192
#define LAM1   8e-05f
#define LAM2   8e-05f

// Scratch (allocation-free rule: __device__ globals)
__device__ float g_base[BS];     // LAM1*smooth + LAM2*spars per row
__device__ int   g_ms[BS];       // argmax index per row
__device__ int   g_hist[SEGLEN]; // histogram of ms over negative rows

// ---------------------------------------------------------------------------
// Kernel 0: zero the histogram (graph replays reuse device globals)
// ---------------------------------------------------------------------------
__global__ __launch_bounds__(1024) void zero_hist() {
    ((int4*)g_hist)[blockIdx.x * 1024 + threadIdx.x] = make_int4(0, 0, 0, 0);
}

// ---------------------------------------------------------------------------
// Kernel 1: per-row sum, sum of squared adjacent diffs, first-occurrence
// argmax. One block per row, 256 threads x 8 float4. Boundary diff element
// comes from the next lane via shuffle (scalar load only on lane 31).
// Thread 0 also bumps the negative-rows argmax histogram (int atomic =>
// deterministic).
// ---------------------------------------------------------------------------
__global__ __launch_bounds__(256) void row_stats(const float* __restrict__ scores,
                                                 const int*   __restrict__ labels) {
    const int row = blockIdx.x;
    const float*  rf = scores + (size_t)row * SEGLEN;
    const float4* rp = (const float4*)rf;
    const int t = threadIdx.x;
    const int lane = t & 31;

    float sum = 0.f, sq = 0.f;
    float maxv = -1.f;
    int   maxi = 0;

#pragma unroll
    for (int k = 0; k < 8; k++) {
        const int v4 = k * 256 + t;   // float4 index; element index e = 4*v4
        const int e  = v4 * 4;
        float4 x = rp[v4];

        // neighbor element e+4 == lane (t+1)'s x.x this iteration
        float nxt = __shfl_down_sync(0xFFFFFFFFu, x.x, 1);
        if (lane == 31)
            nxt = (e + 4 < SEGLEN) ? __ldg(rf + e + 4) : x.w;  // last elem: diff 0

        sum += (x.x + x.y) + (x.z + x.w);
        float d0 = x.y - x.x, d1 = x.z - x.y, d2 = x.w - x.z, d3 = nxt - x.w;
        sq += d0 * d0 + d1 * d1 + d2 * d2 + d3 * d3;

        // strict > preserves first occurrence (per-thread indices increase with k)
        if (x.x > maxv) { maxv = x.x; maxi = e;     }
        if (x.y > maxv) { maxv = x.y; maxi = e + 1; }
        if (x.z > maxv) { maxv = x.z; maxi = e + 2; }
        if (x.w > maxv) { maxv = x.w; maxi = e + 3; }
    }

    // warp reduce (fixed order -> deterministic)
#pragma unroll
    for (int off = 16; off > 0; off >>= 1) {
        sum += __shfl_down_sync(0xFFFFFFFFu, sum, off);
        sq  += __shfl_down_sync(0xFFFFFFFFu, sq,  off);
        float ov = __shfl_down_sync(0xFFFFFFFFu, maxv, off);
        int   oi = __shfl_down_sync(0xFFFFFFFFu, maxi, off);
        if (ov > maxv || (ov == maxv && oi < maxi)) { maxv = ov; maxi = oi; }
    }

    __shared__ float ssum[8], ssq[8], smax[8];
    __shared__ int   sidx[8];
    const int w = t >> 5;
    if (lane == 0) { ssum[w] = sum; ssq[w] = sq; smax[w] = maxv; sidx[w] = maxi; }
    __syncthreads();

    if (t == 0) {
        float S = 0.f, Q = 0.f, M = -1.f;
        int I = 0;
#pragma unroll
        for (int i = 0; i < 8; i++) {
            S += ssum[i];
            Q += ssq[i];
            if (smax[i] > M || (smax[i] == M && sidx[i] < I)) { M = smax[i]; I = sidx[i]; }
        }
        g_base[row] = LAM1 * Q + LAM2 * S;
        g_ms[row]   = I;
        if (labels[row] == 0) atomicAdd(&g_hist[I], 1);
    }
}

// ---------------------------------------------------------------------------
// Kernel 2 (single block, 1024 threads):
//   margin[i] = T[ms[i]] where T = double suffix-sum of g_hist.
//   Suffix scans use a 2-level warp-shuffle scan (2 syncs/round, no
//   Hillis-Steele). Then deterministic reduction over positive rows.
// ---------------------------------------------------------------------------
__global__ __launch_bounds__(1024) void finalize(const int* __restrict__ labels,
                                                 float* __restrict__ out) {
    __shared__ int   cnt[SEGLEN];   // histogram -> S1 -> T (in place)
    __shared__ int   wtot[32];      // per-warp chunk totals
    __shared__ int   woff[32];      // exclusive suffix offsets per warp
    __shared__ float red[32];

    const int t = threadIdx.x;
    const int lane = t & 31, w = t >> 5;
    const int base = t * 8;         // each thread owns bins [8t, 8t+8)

    // load histogram into shared (coalesced)
#pragma unroll
    for (int k = 0; k < 2; k++)
        ((int4*)cnt)[k * 1024 + t] = ((const int4*)g_hist)[k * 1024 + t];
    __syncthreads();

    // two rounds of suffix-sum over 8192 bins
#pragma unroll
    for (int round = 0; round < 2; round++) {
        int c = 0;
#pragma unroll
        for (int k = 0; k < 8; k++) c += cnt[base + k];

        // warp inclusive suffix scan of chunk totals
        int incl = c;
#pragma unroll
        for (int off = 1; off < 32; off <<= 1) {
            int v = __shfl_down_sync(0xFFFFFFFFu, incl, off);
            if (lane + off < 32) incl += v;
        }
        if (lane == 0) wtot[w] = incl;  // lane 0 holds warp total
        __syncthreads();

        // warp 0: exclusive suffix scan over 32 warp totals
        if (w == 0) {
            int v = wtot[lane];
            int s = v;
#pragma unroll
            for (int off = 1; off < 32; off <<= 1) {
                int u = __shfl_down_sync(0xFFFFFFFFu, s, off);
                if (lane + off < 32) s += u;
            }
            woff[lane] = s - v;  // sum of warps > lane
        }
        __syncthreads();

        // exclusive suffix of chunks strictly after this thread's chunk
        int r = (incl - c) + woff[w];
#pragma unroll
        for (int k = 7; k >= 0; k--) {
            r += cnt[base + k];
            cnt[base + k] = r;
        }
        __syncthreads();  // publish before next round's lookups / final reads
    }

    // per-positive-row loss, accumulated in fixed order
    float acc = 0.f;
#pragma unroll
    for (int it = 0; it < BS / 1024; it++) {
        int i = it * 1024 + t;
        if (labels[i] == 1)
            acc += g_base[i] + (float)cnt[g_ms[i]];
    }

    // deterministic tree reduction
#pragma unroll
    for (int off = 16; off > 0; off >>= 1)
        acc += __shfl_down_sync(0xFFFFFFFFu, acc, off);
    if (lane == 0) red[w] = acc;
    __syncthreads();
    if (w == 0) {
        float v = red[lane];
#pragma unroll
        for (int off = 16; off > 0; off >>= 1)
            v += __shfl_down_sync(0xFFFFFFFFu, v, off);
        if (lane == 0) out[0] = v / (float)BS;
    }
}

extern "C" void kernel_launch(void* const* d_in, const int* in_sizes, int n_in,
                              void* d_out, int out_size) {
    const float* scores = (const float*)d_in[0];
    const int*   labels = (const int*)d_in[1];
    float*       out    = (float*)d_out;

    zero_hist<<<2, 1024>>>();
    row_stats<<<BS, 256>>>(scores, labels);
    finalize<<<1, 1024>>>(labels, out);
}

// round 3
// speedup vs baseline: 1.1282x; 1.0110x over previous
#include <cuda_runtime.h>

#define BS     4096
#define SEGLEN 8192
#define LAM1   8e-05f
#define LAM2   8e-05f

// Scratch (allocation-free rule: __device__ globals)
__device__ float g_base[BS];     // LAM1*smooth + LAM2*spars per row
__device__ int   g_ms[BS];       // argmax index per row

// ---------------------------------------------------------------------------
// Kernel 1: per-row sum, sum of squared adjacent diffs, first-occurrence
// argmax. One block per row, 256 threads x 8 float4. Boundary diff element
// comes from the next lane via shuffle (scalar load only on lane 31).
// ---------------------------------------------------------------------------
__global__ __launch_bounds__(256) void row_stats(const float* __restrict__ scores) {
    const int row = blockIdx.x;
    const float*  rf = scores + (size_t)row * SEGLEN;
    const float4* rp = (const float4*)rf;
    const int t = threadIdx.x;
    const int lane = t & 31;

    float sum = 0.f, sq = 0.f;
    float maxv = -1.f;
    int   maxi = 0;

#pragma unroll
    for (int k = 0; k < 8; k++) {
        const int v4 = k * 256 + t;   // float4 index; element index e = 4*v4
        const int e  = v4 * 4;
        float4 x = rp[v4];

        // neighbor element e+4 == lane (t+1)'s x.x this iteration
        float nxt = __shfl_down_sync(0xFFFFFFFFu, x.x, 1);
        if (lane == 31)
            nxt = (e + 4 < SEGLEN) ? __ldg(rf + e + 4) : x.w;  // last elem: diff 0

        sum += (x.x + x.y) + (x.z + x.w);
        float d0 = x.y - x.x, d1 = x.z - x.y, d2 = x.w - x.z, d3 = nxt - x.w;
        sq += d0 * d0 + d1 * d1 + d2 * d2 + d3 * d3;

        // strict > preserves first occurrence (per-thread indices increase with k)
        if (x.x > maxv) { maxv = x.x; maxi = e;     }
        if (x.y > maxv) { maxv = x.y; maxi = e + 1; }
        if (x.z > maxv) { maxv = x.z; maxi = e + 2; }
        if (x.w > maxv) { maxv = x.w; maxi = e + 3; }
    }

    // warp reduce (fixed order -> deterministic)
#pragma unroll
    for (int off = 16; off > 0; off >>= 1) {
        sum += __shfl_down_sync(0xFFFFFFFFu, sum, off);
        sq  += __shfl_down_sync(0xFFFFFFFFu, sq,  off);
        float ov = __shfl_down_sync(0xFFFFFFFFu, maxv, off);
        int   oi = __shfl_down_sync(0xFFFFFFFFu, maxi, off);
        if (ov > maxv || (ov == maxv && oi < maxi)) { maxv = ov; maxi = oi; }
    }

    __shared__ float ssum[8], ssq[8], smax[8];
    __shared__ int   sidx[8];
    const int w = t >> 5;
    if (lane == 0) { ssum[w] = sum; ssq[w] = sq; smax[w] = maxv; sidx[w] = maxi; }
    __syncthreads();

    if (t == 0) {
        float S = 0.f, Q = 0.f, M = -1.f;
        int I = 0;
#pragma unroll
        for (int i = 0; i < 8; i++) {
            S += ssum[i];
            Q += ssq[i];
            if (smax[i] > M || (smax[i] == M && sidx[i] < I)) { M = smax[i]; I = sidx[i]; }
        }
        g_base[row] = LAM1 * Q + LAM2 * S;
        g_ms[row]   = I;
    }
}

// ---------------------------------------------------------------------------
// Kernel 2 (single block, 1024 threads):
//   Histogram of ms over negative rows built directly in SMEM (no global
//   hist, nothing to zero). margin[i] = T[ms[i]] where T = double suffix-sum
//   of the histogram (2-level warp-shuffle suffix scans). Deterministic
//   fixed-order reduction over positive rows.
// ---------------------------------------------------------------------------
__global__ __launch_bounds__(1024) void finalize(const int* __restrict__ labels,
                                                 float* __restrict__ out) {
    __shared__ int   cnt[SEGLEN];   // histogram -> S1 -> T (in place)
    __shared__ int   wtot[32];      // per-warp chunk totals
    __shared__ int   woff[32];      // exclusive suffix offsets per warp
    __shared__ float red[32];
    __shared__ int   s_ms[BS];      // cached argmax indices
    __shared__ int   s_lb[BS];      // cached labels

    const int t = threadIdx.x;
    const int lane = t & 31, w = t >> 5;
    const int base = t * 8;         // each thread owns bins [8t, 8t+8)

#pragma unroll
    for (int k = 0; k < 2; k++) ((int4*)cnt)[k * 1024 + t] = make_int4(0, 0, 0, 0);
    // coalesced cache of ms + labels
    ((int4*)s_ms)[t] = ((const int4*)g_ms)[t];
    ((int4*)s_lb)[t] = ((const int4*)labels)[t];
    __syncthreads();

    // histogram of argmax indices over negative rows (smem atomics)
#pragma unroll
    for (int it = 0; it < BS / 1024; it++) {
        int i = it * 1024 + t;
        if (s_lb[i] == 0) atomicAdd(&cnt[s_ms[i]], 1);
    }
    __syncthreads();

    // two rounds of suffix-sum over 8192 bins
#pragma unroll
    for (int round = 0; round < 2; round++) {
        int c = 0;
#pragma unroll
        for (int k = 0; k < 8; k++) c += cnt[base + k];

        // warp inclusive suffix scan of chunk totals
        int incl = c;
#pragma unroll
        for (int off = 1; off < 32; off <<= 1) {
            int v = __shfl_down_sync(0xFFFFFFFFu, incl, off);
            if (lane + off < 32) incl += v;
        }
        if (lane == 0) wtot[w] = incl;  // warp total
        __syncthreads();

        // warp 0: exclusive suffix scan over 32 warp totals
        if (w == 0) {
            int v = wtot[lane];
            int s = v;
#pragma unroll
            for (int off = 1; off < 32; off <<= 1) {
                int u = __shfl_down_sync(0xFFFFFFFFu, s, off);
                if (lane + off < 32) s += u;
            }
            woff[lane] = s - v;  // sum of warps strictly after lane
        }
        __syncthreads();

        // exclusive suffix of chunks strictly after this thread's chunk
        int r = (incl - c) + woff[w];
#pragma unroll
        for (int k = 7; k >= 0; k--) {
            r += cnt[base + k];
            cnt[base + k] = r;
        }
        __syncthreads();
    }

    // per-positive-row loss, accumulated in fixed order
    float acc = 0.f;
#pragma unroll
    for (int it = 0; it < BS / 1024; it++) {
        int i = it * 1024 + t;
        if (s_lb[i] == 1)
            acc += g_base[i] + (float)cnt[s_ms[i]];
    }

    // deterministic tree reduction
#pragma unroll
    for (int off = 16; off > 0; off >>= 1)
        acc += __shfl_down_sync(0xFFFFFFFFu, acc, off);
    if (lane == 0) red[w] = acc;
    __syncthreads();
    if (w == 0) {
        float v = red[lane];
#pragma unroll
        for (int off = 16; off > 0; off >>= 1)
            v += __shfl_down_sync(0xFFFFFFFFu, v, off);
        if (lane == 0) out[0] = v / (float)BS;
    }
}

extern "C" void kernel_launch(void* const* d_in, const int* in_sizes, int n_in,
                              void* d_out, int out_size) {
    const float* scores = (const float*)d_in[0];
    const int*   labels = (const int*)d_in[1];
    float*       out    = (float*)d_out;

    row_stats<<<BS, 256>>>(scores);
    finalize<<<1, 1024>>>(labels, out);
}